// round 10
// baseline (speedup 1.0000x reference)
#include <cuda_runtime.h>

// CRF loss, bidirectional scaled forward algorithm with ONE DIRECTION PER CTA.
// Grid = 2B CTAs of 64 threads: even CTA = alpha forward (t=0..m), odd CTA =
// beta backward (t=len-1..m) for row b = blockIdx.x>>1. Each direction runs
// on its own SM -> 2 warps on 4 schedulers, no cross-group issue contention,
// cheap 2-warp __syncthreads per step. Midpoint vectors published through
// global scratch; second CTA of the pair combines (deterministic), a global
// atomic ticket does the final fixed-order batch sum.

constexpr int TT = 50;    // tags
constexpr int LL = 256;   // max length
constexpr int NTH = 64;
constexpr int STARTT = TT - 2;
constexpr int STOPT  = TT - 1;

#define LOG2E 1.4426950408889634f
#define LN2F  0.6931471805599453f

__device__ float    g_partial[512];
__device__ float    g_midF[512][64];
__device__ float    g_midB[512][64];
__device__ int      g_kF[512];
__device__ int      g_kB[512];
__device__ float    g_gold[512];
__device__ unsigned g_pair[512];     // zero-init; reset by combiner
__device__ unsigned g_done = 0;      // zero-init; reset by last CTA

__device__ __forceinline__ float ex2(float x) {
    float r;
    asm("ex2.approx.ftz.f32 %0, %1;" : "=f"(r) : "f"(x));
    return r;
}

__device__ __forceinline__ float ldcg(const float* p) {
    float v;
    asm volatile("ld.global.cg.f32 %0, [%1];" : "=f"(v) : "l"(p));
    return v;
}
__device__ __forceinline__ int ldcg_i(const int* p) {
    int v;
    asm volatile("ld.global.cg.s32 %0, [%1];" : "=r"(v) : "l"(p));
    return v;
}

__device__ __forceinline__ float blockSum64(float v, volatile float* red) {
#pragma unroll
    for (int o = 16; o; o >>= 1) v += __shfl_xor_sync(0xffffffffu, v, o);
    if ((threadIdx.x & 31) == 0) red[threadIdx.x >> 5] = v;
    __syncthreads();
    v = red[0] + red[1];
    __syncthreads();
    return v;
}

__global__ void __launch_bounds__(NTH, 1)
crf_kernel(const float* __restrict__ feats, const float* __restrict__ trans,
           const int* __restrict__ tags, const int* __restrict__ mask,
           float* __restrict__ out) {
    __shared__ __align__(16) float Pb[2][64];
    __shared__ float red[2];
    __shared__ int s_len;
    __shared__ unsigned s_rank;

    const int b    = blockIdx.x >> 1;
    const bool isF = (blockIdx.x & 1) == 0;
    const int tid  = threadIdx.x;
    const bool gv  = (tid < TT);
    const int gc   = gv ? tid : (TT - 1);

    if (tid == 0) s_len = 0;
    __syncthreads();

    // ---- sequence length (mask is a 0/1 prefix) ----
    {
        const int4* m4 = (const int4*)(mask + (size_t)b * LL);
        int4 v = m4[tid];
        int c = (v.x != 0) + (v.y != 0) + (v.z != 0) + (v.w != 0);
#pragma unroll
        for (int o = 16; o; o >>= 1) c += __shfl_xor_sync(0xffffffffu, c, o);
        if ((tid & 31) == 0) atomicAdd(&s_len, c);
    }

    // ---- E in registers: forward thread j holds column E[:,j];
    //      backward thread i holds row E[i,:] ----
    const float* tb = isF ? (trans + gc) : (trans + gc * TT);
    const int    ts = isF ? TT : 1;
    float E[52];
#pragma unroll
    for (int x = 0; x < TT; x++) E[x] = gv ? ex2(tb[x * ts] * LOG2E) : 0.f;
    E[50] = 0.f; E[51] = 0.f;

    const float* fb = feats + (size_t)b * LL * TT;
    const float s0   = trans[STARTT * TT + 1];
    const float tref = trans[1 * TT + STOPT];

    __syncthreads();
    const int len = s_len;
    const int nf  = (len - 1) >> 1;        // forward steps
    const int nb  = (len - 1) - nf;        // backward steps (>= nf)

    // ---- init ----
    if (isF) {
        Pb[0][tid] = gv ? ex2((fb[gc] + trans[STARTT * TT + gc] - s0) * LOG2E)
                        : 0.f;
    } else {
        float w = gv ? ex2((trans[gc * TT + STOPT] - tref) * LOG2E) : 0.f;
        float f = (nb > 0) ? ex2(fb[(len - 1) * TT + gc] * LOG2E) : 1.f;
        Pb[0][tid] = gv ? w * f : 0.f;
    }
    int kacc = 0;

    // ---- distance-2 feats prefetch (clamped) ----
    int r1 = isF ? 1 : len - 2;
    int r2 = isF ? 2 : len - 3;
    r1 = min(max(r1, 0), len - 1);
    r2 = min(max(r2, 0), len - 1);
    float fc = fb[r1 * TT + gc];
    float fn = fb[r2 * TT + gc];

    float* Pc = Pb[0];
    float* Pn = Pb[1];
    __syncthreads();

#define CRF_STEP(EFV)                                                     \
    {                                                                     \
        const float4* p4 = (const float4*)Pc;                             \
        float4 v0 = p4[0];                                                \
        float m = fmaxf(fmaxf(v0.y, v0.z), v0.w);                         \
        int   k = (__float_as_int(m) >> 23) - 127;                        \
        float sf = __int_as_float((127 - k) << 23) * (EFV);               \
        float a0 = v0.x * E[0], a1 = v0.y * E[1];                         \
        float a2 = v0.z * E[2], a3 = v0.w * E[3];                         \
        float b0 = 0.f, b1 = 0.f, b2 = 0.f, b3 = 0.f;                     \
        _Pragma("unroll")                                                 \
        for (int q = 1; q < 13; q += 2) {                                 \
            float4 v = p4[q];                                             \
            a0 = fmaf(v.x, E[4 * q + 0], a0);                             \
            a1 = fmaf(v.y, E[4 * q + 1], a1);                             \
            a2 = fmaf(v.z, E[4 * q + 2], a2);                             \
            a3 = fmaf(v.w, E[4 * q + 3], a3);                             \
        }                                                                 \
        _Pragma("unroll")                                                 \
        for (int q = 2; q < 13; q += 2) {                                 \
            float4 v = p4[q];                                             \
            b0 = fmaf(v.x, E[4 * q + 0], b0);                             \
            b1 = fmaf(v.y, E[4 * q + 1], b1);                             \
            b2 = fmaf(v.z, E[4 * q + 2], b2);                             \
            b3 = fmaf(v.w, E[4 * q + 3], b3);                             \
        }                                                                 \
        float acc = ((a0 + b0) + (a1 + b1)) + ((a2 + b2) + (a3 + b3));    \
        Pn[tid] = acc * sf;                                               \
        kacc += k;                                                        \
        __syncthreads();                                                  \
        float* _t = Pc; Pc = Pn; Pn = _t;                                 \
    }

    if (isF) {
        for (int s = 1; s <= nf; ++s) {
            float efv = ex2(fc * LOG2E);
            fc = fn;
            int rn = min(s + 2, len - 1);
            fn = fb[rn * TT + gc];
            CRF_STEP(efv);
        }
    } else {
        for (int s = 1; s < nb; ++s) {
            float efv = ex2(fc * LOG2E);
            fc = fn;
            int rn = max(len - 3 - s, 0);
            fn = fb[rn * TT + gc];
            CRF_STEP(efv);
        }
        if (nb >= 1) {                  // final step: exclude ef_m
            CRF_STEP(1.0f);
        }
    }
#undef CRF_STEP

    // ---- publish midpoint; forward also computes the gold score ----
    if (isF) {
        const int* tgb = tags + (size_t)b * LL;
        float gl = 0.f;
        for (int t = tid; t < len; t += NTH) {
            int tg = tgb[t];
            int pv = (t == 0) ? STARTT : tgb[t - 1];
            gl += fb[t * TT + tg] + trans[pv * TT + tg];
        }
        float gold = blockSum64(gl, red);
        g_midF[b][tid] = Pc[tid];
        if (tid == 0) {
            g_kF[b] = kacc;
            g_gold[b] = gold + trans[tgb[len - 1] * TT + STOPT];
        }
    } else {
        g_midB[b][tid] = Pc[tid];
        if (tid == 0) g_kB[b] = kacc;
    }
    __threadfence();
    if (tid == 0) s_rank = atomicAdd(&g_pair[b], 1u);
    __syncthreads();

    // ---- second of the pair combines (identical math either way) ----
    if (s_rank == 1) {
        float av = ldcg(&g_midF[b][tid]);
        float bv = ldcg(&g_midB[b][tid]);
        float sumv = blockSum64(av * bv, red);
        if (tid == 0) {
            int kf = ldcg_i(&g_kF[b]);
            int kb = ldcg_i(&g_kB[b]);
            float fwd = (log2f(sumv) + s0 * LOG2E + (float)(kf + kb)) * LN2F
                        + tref;
            g_partial[b] = fwd - ldcg(&g_gold[b]);
            g_pair[b] = 0;              // reset for next graph replay
        }
        __threadfence();
    }

    // ---- global finalize: last CTA sums all partials (fixed order) ----
    if (tid == 0) s_rank = atomicAdd(&g_done, 1u);
    __syncthreads();
    if (s_rank == gridDim.x - 1) {
        const int B = gridDim.x >> 1;
        if (tid < 32) {
            float acc = 0.f;
            for (int i = tid; i < B; i += 32) acc += ldcg(&g_partial[i]);
#pragma unroll
            for (int o = 16; o; o >>= 1)
                acc += __shfl_xor_sync(0xffffffffu, acc, o);
            if (tid == 0) {
                *out = acc;
                g_done = 0;             // reset for next graph replay
            }
        }
    }
}

extern "C" void kernel_launch(void* const* d_in, const int* in_sizes, int n_in,
                              void* d_out, int out_size) {
    const float* feats = (const float*)d_in[0];
    const float* trans = (const float*)d_in[1];
    const int*   tags  = (const int*)d_in[2];
    const int*   mask  = (const int*)d_in[3];
    int B = in_sizes[0] / (LL * TT);

    crf_kernel<<<2 * B, NTH>>>(feats, trans, tags, mask, (float*)d_out);
}

// round 11
// speedup vs baseline: 1.4763x; 1.4763x over previous
#include <cuda_runtime.h>
#include <cstdint>

// CRF loss via bidirectional scaled forward algorithm, f32x2-packed inner loop.
// One 128-thread CTA per batch row: warps 0-1 alpha forward (t=0..m), warps
// 2-3 beta backward (t=len-1..m); Z = sum_i alpha_m[i]*beta_m[i]. Each group
// has its own named barrier and tight loop. The 50-term dot product per
// thread runs as 26 fma.rn.f32x2 (packed fp32 pairs, sm_100+) on pairs loaded
// with ld.shared.v2.u64 against pre-packed E registers — half the issue
// slots of the scalar version, bit-identical fp32 math.

constexpr int TT = 50;
constexpr int LL = 256;
constexpr int NTH = 128;
constexpr int STARTT = TT - 2;
constexpr int STOPT  = TT - 1;

#define LOG2E 1.4426950408889634f
#define LN2F  0.6931471805599453f

__device__ float    g_partial[1024];
__device__ unsigned g_done = 0;

__device__ __forceinline__ float ex2(float x) {
    float r;
    asm("ex2.approx.ftz.f32 %0, %1;" : "=f"(r) : "f"(x));
    return r;
}

__device__ __forceinline__ void barg(int id) {    // group barrier, 64 threads
    asm volatile("bar.sync %0, 64;" :: "r"(id));
}

#define PACK2(d, lo, hi) \
    asm("mov.b64 %0, {%1, %2};" : "=l"(d) : "f"(lo), "f"(hi))
#define UNPACK2(lo, hi, s) \
    asm("mov.b64 {%0, %1}, %2;" : "=f"(lo), "=f"(hi) : "l"(s))
#define FFMA2(d, a, b, c) \
    asm("fma.rn.f32x2 %0, %1, %2, %3;" : "=l"(d) : "l"(a), "l"(b), "l"(c))
#define FMUL2(d, a, b) \
    asm("mul.rn.f32x2 %0, %1, %2;" : "=l"(d) : "l"(a), "l"(b))
#define FADD2(d, a, b) \
    asm("add.rn.f32x2 %0, %1, %2;" : "=l"(d) : "l"(a), "l"(b))
#define LDS_V2U64(q0, q1, addr) \
    asm volatile("ld.shared.v2.u64 {%0, %1}, [%2];" \
                 : "=l"(q0), "=l"(q1) : "r"(addr))

__device__ __forceinline__ float blockSum(float v, volatile float* red) {
#pragma unroll
    for (int o = 16; o; o >>= 1) v += __shfl_xor_sync(0xffffffffu, v, o);
    if ((threadIdx.x & 31) == 0) red[threadIdx.x >> 5] = v;
    __syncthreads();
    v = (red[0] + red[1]) + (red[2] + red[3]);
    __syncthreads();
    return v;
}

__global__ void __launch_bounds__(NTH, 1)
crf_kernel(const float* __restrict__ feats, const float* __restrict__ trans,
           const int* __restrict__ tags, const int* __restrict__ mask,
           float* __restrict__ out) {
    __shared__ __align__(16) float Ab[2][64];   // alpha ping-pong
    __shared__ __align__(16) float Bb[2][64];   // beta  ping-pong
    __shared__ float red[4];
    __shared__ int s_len, s_kf, s_kb;
    __shared__ unsigned s_rank;

    const int b    = blockIdx.x;
    const int tid  = threadIdx.x;
    const bool isF = (tid < 64);       // forward group = warps 0-1
    const int g    = tid & 63;         // state index within group
    const bool gv  = (g < TT);
    const int gc   = gv ? g : (TT - 1);
    const int bid  = isF ? 1 : 2;

    if (tid == 0) s_len = 0;
    __syncthreads();

    // ---- sequence length (mask is a 0/1 prefix) ----
    {
        const int2* m2 = (const int2*)(mask + (size_t)b * LL);
        int2 v = m2[tid];
        int c = (v.x != 0) + (v.y != 0);
#pragma unroll
        for (int o = 16; o; o >>= 1) c += __shfl_xor_sync(0xffffffffu, c, o);
        if ((tid & 31) == 0) atomicAdd(&s_len, c);
    }

    // ---- E packed in registers: pair x holds (E[2x], E[2x+1]) of my slice
    //      forward thread j: E[i] = exp(trans[i][j]) (column)
    //      backward thread i: E[i] = exp(trans[i][x]) (row) ----
    const float* tb = isF ? (trans + gc) : (trans + gc * TT);
    const int    ts = isF ? TT : 1;
    uint64_t E2[26];
#pragma unroll
    for (int x = 0; x < 26; x++) {
        int i0 = 2 * x, i1 = 2 * x + 1;
        float e0 = (gv && i0 < TT) ? ex2(tb[i0 * ts] * LOG2E) : 0.f;
        float e1 = (gv && i1 < TT) ? ex2(tb[i1 * ts] * LOG2E) : 0.f;
        PACK2(E2[x], e0, e1);
    }

    const float* fb = feats + (size_t)b * LL * TT;
    const float s0   = trans[STARTT * TT + 1];
    const float tref = trans[1 * TT + STOPT];
    const float C2f  = s0 * LOG2E;

    __syncthreads();
    const int len = s_len;
    const int nf  = (len - 1) >> 1;        // forward steps
    const int nb  = (len - 1) - nf;        // backward steps (>= nf)

    // ---- group inits (all 64 slots written; cols >= 50 exact zero) ----
    if (isF) {
        Ab[0][g] = gv ? ex2((fb[gc] + trans[STARTT * TT + gc] - s0) * LOG2E)
                      : 0.f;
    } else {
        float w = gv ? ex2((trans[gc * TT + STOPT] - tref) * LOG2E) : 0.f;
        float f = (nb > 0) ? ex2(fb[(len - 1) * TT + gc] * LOG2E) : 1.f;
        Bb[0][g] = gv ? w * f : 0.f;
    }
    int kacc = 0;

    // ---- distance-2 feats prefetch (clamped) ----
    int r1 = isF ? 1 : len - 2;
    int r2 = isF ? 2 : len - 3;
    r1 = min(max(r1, 0), len - 1);
    r2 = min(max(r2, 0), len - 1);
    float fc = fb[r1 * TT + gc];
    float fn = fb[r2 * TT + gc];

    float* Pc = isF ? Ab[0] : Bb[0];
    float* Pn = isF ? Ab[1] : Bb[1];
    barg(bid);

    // one step: packed 52-term dot (26 FFMA2) + exact pow2 rescale + store
#define CRF_STEP(EFV)                                                       \
    {                                                                       \
        unsigned sc_ = (unsigned)__cvta_generic_to_shared(Pc);              \
        uint64_t q0, q1;                                                    \
        uint64_t acc0, acc1, acc2, acc3, acc4, acc5, acc6, acc7;            \
        LDS_V2U64(q0, q1, sc_);                                             \
        /* pivot from pair q1 = (P[2],P[3]) and q0.hi = P[1] */             \
        float pv0, pv1, pv2, pv3;                                           \
        UNPACK2(pv0, pv1, q0);                                              \
        UNPACK2(pv2, pv3, q1);                                              \
        float m_ = fmaxf(fmaxf(pv1, pv2), pv3);                             \
        int   k_ = (__float_as_int(m_) >> 23) - 127;                        \
        float sf = __int_as_float((127 - k_) << 23) * (EFV);                \
        FMUL2(acc0, q0, E2[0]);                                             \
        FMUL2(acc1, q1, E2[1]);                                             \
        LDS_V2U64(q0, q1, sc_ + 16);                                        \
        FMUL2(acc2, q0, E2[2]);                                             \
        FMUL2(acc3, q1, E2[3]);                                             \
        LDS_V2U64(q0, q1, sc_ + 32);                                        \
        FMUL2(acc4, q0, E2[4]);                                             \
        FMUL2(acc5, q1, E2[5]);                                             \
        LDS_V2U64(q0, q1, sc_ + 48);                                        \
        FMUL2(acc6, q0, E2[6]);                                             \
        FMUL2(acc7, q1, E2[7]);                                             \
        _Pragma("unroll")                                                   \
        for (int q = 4; q < 13; q++) {                                      \
            LDS_V2U64(q0, q1, sc_ + q * 16);                                \
            FFMA2(acc0, q0, E2[2 * q], acc0);                               \
            FFMA2(acc1, q1, E2[2 * q + 1], acc1);                           \
            uint64_t t0 = acc0; acc0 = acc2; acc2 = acc4; acc4 = acc6;      \
            acc6 = t0;                                                      \
            uint64_t t1 = acc1; acc1 = acc3; acc3 = acc5; acc5 = acc7;      \
            acc7 = t1;                                                      \
        }                                                                   \
        FADD2(acc0, acc0, acc4);                                            \
        FADD2(acc1, acc1, acc5);                                            \
        FADD2(acc2, acc2, acc6);                                            \
        FADD2(acc3, acc3, acc7);                                            \
        FADD2(acc0, acc0, acc2);                                            \
        FADD2(acc1, acc1, acc3);                                            \
        FADD2(acc0, acc0, acc1);                                            \
        float lo_, hi_;                                                     \
        UNPACK2(lo_, hi_, acc0);                                            \
        Pn[g] = (lo_ + hi_) * sf;                                           \
        kacc += k_;                                                         \
        barg(bid);                                                          \
        float* _t = Pc; Pc = Pn; Pn = _t;                                   \
    }

    if (isF) {
        for (int s = 1; s <= nf; ++s) {
            float efv = ex2(fc * LOG2E);
            fc = fn;
            int rn = min(s + 2, len - 1);
            fn = fb[rn * TT + gc];
            CRF_STEP(efv);
        }
    } else {
        for (int s = 1; s < nb; ++s) {
            float efv = ex2(fc * LOG2E);
            fc = fn;
            int rn = max(len - 3 - s, 0);
            fn = fb[rn * TT + gc];
            CRF_STEP(efv);
        }
        if (nb >= 1) {                  // final step: exclude ef_m
            CRF_STEP(1.0f);
        }
    }
#undef CRF_STEP

    // ---- combine at the midpoint: Z = sum_i alpha_m[i] * beta_m[i] ----
    if (tid == 0)  s_kf = kacc;
    if (tid == 64) s_kb = kacc;
    __syncthreads();
    float z = 0.f;
    if (isF && gv) z = Pc[g] * Bb[nb & 1][g];
    float sumv = blockSum(z, red);
    float fwd = (log2f(sumv) + C2f + (float)(s_kf + s_kb)) * LN2F + tref;

    // ---- gold score ----
    const int* tgb = tags + (size_t)b * LL;
    float gl = 0.f;
    for (int t = tid; t < len; t += NTH) {
        int tg = tgb[t];
        int pv = (t == 0) ? STARTT : tgb[t - 1];
        gl += fb[t * TT + tg] + trans[pv * TT + tg];
    }
    float gold = blockSum(gl, red);

    if (tid == 0) {
        gold += trans[tgb[len - 1] * TT + STOPT];
        g_partial[b] = fwd - gold;
    }

    // ---- fused finalize: last CTA sums all partials (fixed order) ----
    __threadfence();
    if (tid == 0) s_rank = atomicAdd(&g_done, 1u);
    __syncthreads();
    if (s_rank == gridDim.x - 1) {
        const int B = gridDim.x;
        if (tid < 32) {
            float acc = 0.f;
            for (int i = tid; i < B; i += 32) {
                float v;
                asm volatile("ld.global.cg.f32 %0, [%1];" : "=f"(v)
                             : "l"(&g_partial[i]));
                acc += v;
            }
#pragma unroll
            for (int o = 16; o; o >>= 1)
                acc += __shfl_xor_sync(0xffffffffu, acc, o);
            if (tid == 0) {
                *out = acc;
                g_done = 0;   // reset for next graph replay
            }
        }
    }
}

extern "C" void kernel_launch(void* const* d_in, const int* in_sizes, int n_in,
                              void* d_out, int out_size) {
    const float* feats = (const float*)d_in[0];
    const float* trans = (const float*)d_in[1];
    const int*   tags  = (const int*)d_in[2];
    const int*   mask  = (const int*)d_in[3];
    int B = in_sizes[0] / (LL * TT);

    crf_kernel<<<B, NTH>>>(feats, trans, tags, mask, (float*)d_out);
}